// round 13
// baseline (speedup 1.0000x reference)
#include <cuda_runtime.h>
#include <cuda_bf16.h>
#include <math.h>
#include <stdint.h>

// Problem constants
#define BB 512
#define KK 256
#define NN 512
#define CC 6
#define JP (KK/2)       // 128 k-pairs
#define HALF_N 256      // tracks per block (2 blocks per batch)
#define TPB 128         // threads per block; each thread owns 2 tracks

#define LOG2E_F 1.4426950408889634f
#define LN2_F   0.6931471805599453f
#define LOG2PI_LOG2E_F 2.6514961294723187f  // log2(2*pi)
#define RQ2_F 0.72134752044448170f          // 0.5 * log2(e)

// ---------------- scratch (static device globals; no allocation) -------------
__device__ double4 g_part[2 * BB];           // {spatial, efs, cnt, lam} per block
__device__ unsigned int g_done = 0;

// ---------------- fast math helpers ------------------------------------------
__device__ __forceinline__ float ex2f(float x) {
    float y; asm("ex2.approx.ftz.f32 %0, %1;" : "=f"(y) : "f"(x)); return y;
}
__device__ __forceinline__ float lg2f(float x) {
    float y; asm("lg2.approx.ftz.f32 %0, %1;" : "=f"(y) : "f"(x)); return y;
}

// FMA/ALU-pipe exp2 for q <= 0 (no MUFU). Magic-round + exponent assembly +
// degree-5 poly on f in [-0.5, 0.5]. Underflow clamps to ~2^-126 (negligible
// vs the dominant mixture component; s is always >> 2^-120 here).
__device__ __forceinline__ float exp2poly(float q) {
    const float C = 12582912.0f;            // 1.5 * 2^23
    float y = q + C;                         // round-to-nearest-int in mantissa
    float f = q - (y - C);                   // f in [-0.5, 0.5]
    int iv = __float_as_int(y);
    iv = max(iv, 0x4B400000 - 126);          // clamp n >= -126
    float scale = __int_as_float((iv + (127 - 0x4B400000)) << 23);  // 2^n
    float r = fmaf(1.33335581e-3f, f, 9.61812911e-3f);
    r = fmaf(r, f, 5.55041087e-2f);
    r = fmaf(r, f, 2.40226507e-1f);
    r = fmaf(r, f, 6.93147181e-1f);
    r = fmaf(r, f, 1.0f);
    return r * scale;
}

__device__ __forceinline__ double warpRedD(double v) {
    #pragma unroll
    for (int o = 16; o; o >>= 1) v += __shfl_down_sync(0xffffffffu, v, o);
    return v;
}

// ---------------- main kernel (fully fused) -----------------------------------
__global__ __launch_bounds__(TPB) void main_kernel(
    const float* __restrict__ pi,
    const float* __restrict__ mu,
    const float* __restrict__ L,
    const float* __restrict__ ef_logits,
    const float* __restrict__ tracks,
    const uint32_t* __restrict__ mask,
    float* __restrict__ out)
{
    const int bid  = blockIdx.x;
    const int b    = bid >> 1;
    const int half = bid & 1;
    const int tid  = threadIdx.x;

    __shared__ float4 scA[KK];         // {c0,c1,c2,c3} per k          4 KB
    __shared__ float4 scB[JP];         // {c4_k0,c5_k0,c4_k1,c5_k1}    2 KB
    __shared__ float2 sce2[JP * CC];   // {ce(2j,g), ce(2j+1,g)}       6 KB
    __shared__ double red[4 * 4];
    __shared__ bool   isLast;

    // Lambda contribution: only half 0 accumulates pi (each thread covers 2 k's)
    double lam = 0.0;
    if (half == 0) {
        lam = (double)pi[(size_t)b * KK + tid] + (double)pi[(size_t)b * KK + tid + TPB];
    }

    const int n0 = half * HALF_N;
    // prefix-mask property: first inactive => whole 256-track range inactive
    const bool blockActive = (mask[(size_t)b * NN + n0] != 0u);

    double spatial = 0.0, efs = 0.0, cnt = 0.0;

    if (blockActive) {
        // ---- staging (float): thread tid builds coefficients for k=tid, tid+128 ----
        #pragma unroll
        for (int kk = 0; kk < 2; kk++) {
            const int k = tid + kk * TPB;
            const int i = b * KK + k;
            float pv = pi[i];
            float a  = L[i * 4 + 0];
            float bb = L[i * 4 + 2];
            float c  = L[i * 4 + 3];
            float m0 = mu[i * 2 + 0];
            float m1 = mu[i * 2 + 1];

            float base2 = lg2f(pv) - LOG2PI_LOG2E_F - lg2f(a * c);  // < 0

            float A2  = RQ2_F / (a * a);
            float Cr2 = RQ2_F / (c * c);
            float BA  = bb / a;
            float P = fmaf(Cr2 * BA, BA, A2);
            float Q = Cr2;
            float R = -2.0f * Cr2 * BA;

            float4 v4;
            v4.x = base2 - P * m0 * m0 - Q * m1 * m1 - R * m0 * m1;
            v4.y = fmaf(2.0f * P, m0, R * m1);
            v4.z = fmaf(2.0f * Q, m1, R * m0);
            v4.w = -P;
            scA[k] = v4;

            const int j = k >> 1, lane = k & 1;
            float* fB = (float*)scB;
            fB[j * 4 + lane * 2 + 0] = -Q;
            fB[j * 4 + lane * 2 + 1] = -R;

            // CE table: lse(ef_logits) - ef_logits[c], paired layout
            float e[CC];
            float mx = -INFINITY;
            #pragma unroll
            for (int c2 = 0; c2 < CC; c2++) {
                e[c2] = ef_logits[(size_t)i * CC + c2];
                mx = fmaxf(mx, e[c2]);
            }
            float ssum = 0.f;
            #pragma unroll
            for (int c2 = 0; c2 < CC; c2++) ssum += ex2f((e[c2] - mx) * LOG2E_F);
            float lse = mx + lg2f(ssum) * LN2_F;
            float* fce = (float*)sce2;
            #pragma unroll
            for (int c2 = 0; c2 < CC; c2++) fce[(j * CC + c2) * 2 + lane] = lse - e[c2];
        }
        __syncthreads();

        // ---- per-track pass: thread owns tracks n0+tid (A) and n0+tid+128 (B) ----
        const int nA = n0 + tid;
        const int nB = nA + TPB;
        const bool actA = (mask[(size_t)b * NN + nA] != 0u);
        const bool actB = (mask[(size_t)b * NN + nB] != 0u);
        const bool anyA = (__ballot_sync(0xffffffffu, actA) != 0u);
        const bool anyB = (__ballot_sync(0xffffffffu, actB) != 0u);

        if (anyA) {
            const float* trA = tracks + ((size_t)b * NN + nA) * 6;
            const float* trB = tracks + ((size_t)b * NN + nB) * 6;
            float x0A = trA[0], x1A = trA[1];
            int   gA  = (int)trA[5];
            const float2* cepA = sce2 + gA;

            float sA = 0.f, tA = 0.f;

            if (anyB) {
                float x0B = trB[0], x1B = trB[1];
                int   gB  = (int)trB[5];
                const float2* cepB = sce2 + gB;
                float sB = 0.f, tB = 0.f;

                #pragma unroll 2
                for (int j = 0; j < JP; j++) {
                    const float4 a0  = scA[2 * j];
                    const float4 a1  = scA[2 * j + 1];
                    const float4 bbq = scB[j];
                    const float2 ceA = cepA[j * CC];
                    const float2 ceB = cepB[j * CC];

                    // Horner: q = c0 + (c1 + c3*x0)*x0 + (c2 + c5*x0 + c4*x1)*x1
                    float u1A = fmaf(a0.w, x0A, a0.y);
                    float u2A = fmaf(bbq.y, x0A, a0.z);
                    u2A = fmaf(bbq.x, x1A, u2A);
                    float qA0 = fmaf(u1A, x0A, a0.x);
                    qA0 = fmaf(u2A, x1A, qA0);

                    float u1B = fmaf(a0.w, x0B, a0.y);
                    float u2B = fmaf(bbq.y, x0B, a0.z);
                    u2B = fmaf(bbq.x, x1B, u2B);
                    float qB0 = fmaf(u1B, x0B, a0.x);
                    qB0 = fmaf(u2B, x1B, qB0);

                    float v1A = fmaf(a1.w, x0A, a1.y);
                    float v2A = fmaf(bbq.w, x0A, a1.z);
                    v2A = fmaf(bbq.z, x1A, v2A);
                    float qA1 = fmaf(v1A, x0A, a1.x);
                    qA1 = fmaf(v2A, x1A, qA1);

                    float v1B = fmaf(a1.w, x0B, a1.y);
                    float v2B = fmaf(bbq.w, x0B, a1.z);
                    v2B = fmaf(bbq.z, x1B, v2B);
                    float qB1 = fmaf(v1B, x0B, a1.x);
                    qB1 = fmaf(v2B, x1B, qB1);

                    float pA0 = exp2poly(qA0);
                    float pB0 = exp2poly(qB0);
                    float pA1 = exp2poly(qA1);
                    float pB1 = exp2poly(qB1);

                    sA += pA0;
                    sB += pB0;
                    sA += pA1;
                    sB += pB1;
                    tA = fmaf(pA0, ceA.x, tA);
                    tB = fmaf(pB0, ceB.x, tB);
                    tA = fmaf(pA1, ceA.y, tA);
                    tB = fmaf(pB1, ceB.y, tB);
                }
                if (actB) {
                    spatial -= (double)(lg2f(sB) * LN2_F);
                    efs     += (double)(tB / sB);
                    cnt     += 1.0;
                }
            } else {
                #pragma unroll 2
                for (int j = 0; j < JP; j++) {
                    const float4 a0  = scA[2 * j];
                    const float4 a1  = scA[2 * j + 1];
                    const float4 bbq = scB[j];
                    const float2 ceA = cepA[j * CC];

                    float u1A = fmaf(a0.w, x0A, a0.y);
                    float u2A = fmaf(bbq.y, x0A, a0.z);
                    u2A = fmaf(bbq.x, x1A, u2A);
                    float qA0 = fmaf(u1A, x0A, a0.x);
                    qA0 = fmaf(u2A, x1A, qA0);

                    float v1A = fmaf(a1.w, x0A, a1.y);
                    float v2A = fmaf(bbq.w, x0A, a1.z);
                    v2A = fmaf(bbq.z, x1A, v2A);
                    float qA1 = fmaf(v1A, x0A, a1.x);
                    qA1 = fmaf(v2A, x1A, qA1);

                    float pA0 = exp2poly(qA0);
                    float pA1 = exp2poly(qA1);
                    sA += pA0;
                    sA += pA1;
                    tA = fmaf(pA0, ceA.x, tA);
                    tA = fmaf(pA1, ceA.y, tA);
                }
            }
            if (actA) {
                spatial -= (double)(lg2f(sA) * LN2_F);
                efs     += (double)(tA / sA);
                cnt     += 1.0;
            }
        }
    }

    // ---- block reduce 4 doubles (uniform control, 4 warps) ----
    spatial = warpRedD(spatial);
    efs     = warpRedD(efs);
    cnt     = warpRedD(cnt);
    lam     = warpRedD(lam);
    const int wid = tid >> 5, lid = tid & 31;
    if (lid == 0) {
        red[wid]      = spatial;
        red[4 + wid]  = efs;
        red[8 + wid]  = cnt;
        red[12 + wid] = lam;
    }
    __syncthreads();
    if (tid == 0) {
        double s0 = 0, s1 = 0, s2 = 0, s3 = 0;
        #pragma unroll
        for (int w = 0; w < 4; w++) {
            s0 += red[w]; s1 += red[4 + w]; s2 += red[8 + w]; s3 += red[12 + w];
        }
        g_part[bid] = make_double4(s0, s1, s2, s3);
    }

    // ---- last-block-done finalize (deterministic fixed-order sum) ----
    __threadfence();
    if (tid == 0) {
        unsigned int v = atomicAdd(&g_done, 1u);
        isLast = (v == 2u * BB - 1u);
    }
    __syncthreads();
    if (isLast) {
        double lamSum = 0, cntSum = 0, l1Sum = 0, spSum = 0, efSum = 0;
        for (int b2 = tid; b2 < BB; b2 += TPB) {
            double4 e0 = g_part[2 * b2];
            double4 e1 = g_part[2 * b2 + 1];
            double sp = e0.x + e1.x;
            double ef = e0.y + e1.y;
            double gc = e0.z + e1.z;
            double lm = e0.w + e1.w;
            lamSum += lm;
            cntSum += gc;
            l1Sum  += fabs(lm - gc) * sqrt(gc + 1.0);
            spSum  += sp;
            efSum  += ef;
        }
        lamSum = warpRedD(lamSum);
        cntSum = warpRedD(cntSum);
        l1Sum  = warpRedD(l1Sum);
        spSum  = warpRedD(spSum);
        efSum  = warpRedD(efSum);
        __syncthreads();
        __shared__ double red5[4 * 5];
        if (lid == 0) {
            red5[wid]      = lamSum;
            red5[4 + wid]  = cntSum;
            red5[8 + wid]  = l1Sum;
            red5[12 + wid] = spSum;
            red5[16 + wid] = efSum;
        }
        __syncthreads();
        if (tid == 0) {
            double a0 = 0, a1 = 0, a2 = 0, a3 = 0, a4 = 0;
            #pragma unroll
            for (int w = 0; w < 4; w++) {
                a0 += red5[w]; a1 += red5[4 + w]; a2 += red5[8 + w];
                a3 += red5[12 + w]; a4 += red5[16 + w];
            }
            double count_loss = a0 / (double)BB;
            double n_total    = a1 > 1.0 ? a1 : 1.0;
            double count_l1   = a2 / (double)BB;
            double spatialL   = a3 / n_total;
            double efL        = a4 / n_total;
            double total = count_loss + spatialL + efL + count_l1;
            out[0] = (float)total;
            out[1] = (float)spatialL;
            out[2] = (float)count_loss;
            out[3] = (float)count_l1;
            out[4] = (float)efL;
            g_done = 0;  // reset for next graph replay
        }
    }
}

// ---------------- launch -------------------------------------------------------
extern "C" void kernel_launch(void* const* d_in, const int* in_sizes, int n_in,
                              void* d_out, int out_size) {
    const float* pi        = (const float*)d_in[0];
    const float* mu        = (const float*)d_in[1];
    const float* L         = (const float*)d_in[2];
    const float* ef_logits = (const float*)d_in[3];
    const float* tracks    = (const float*)d_in[4];
    const uint32_t* mask   = (const uint32_t*)d_in[5];

    main_kernel<<<2 * BB, TPB>>>(pi, mu, L, ef_logits, tracks, mask, (float*)d_out);
}

// round 14
// speedup vs baseline: 1.5009x; 1.5009x over previous
#include <cuda_runtime.h>
#include <cuda_bf16.h>
#include <cuda_fp16.h>
#include <math.h>
#include <stdint.h>

// Problem constants
#define BB 512
#define KK 256
#define NN 512
#define CC 6
#define JP (KK/2)       // 128 k-pairs
#define HALF_N 256      // tracks per block (2 blocks per batch)
#define TPB 128         // threads per block; each thread owns 2 tracks

#define LOG2E_F 1.4426950408889634f
#define LN2_F   0.6931471805599453f
#define LOG2PI_LOG2E_F 2.6514961294723187f  // log2(2*pi)
#define RQ2_F 0.72134752044448170f          // 0.5 * log2(e)

// ---------------- scratch (static device globals; no allocation) -------------
__device__ double4 g_part[2 * BB];           // {spatial, efs, cnt, lam} per block
__device__ unsigned int g_done = 0;

// ---------------- fast math helpers ------------------------------------------
__device__ __forceinline__ float ex2f(float x) {
    float y; asm("ex2.approx.ftz.f32 %0, %1;" : "=f"(y) : "f"(x)); return y;
}
__device__ __forceinline__ float lg2f(float x) {
    float y; asm("lg2.approx.ftz.f32 %0, %1;" : "=f"(y) : "f"(x)); return y;
}
// dual-half exp2: one MUFU op computes 2^x for both halves
__device__ __forceinline__ __half2 h2ex2(__half2 x) {
    uint32_t xi = *reinterpret_cast<uint32_t*>(&x), yi;
    asm("ex2.approx.f16x2 %0, %1;" : "=r"(yi) : "r"(xi));
    return *reinterpret_cast<__half2*>(&yi);
}
__device__ __forceinline__ double warpRedD(double v) {
    #pragma unroll
    for (int o = 16; o; o >>= 1) v += __shfl_down_sync(0xffffffffu, v, o);
    return v;
}

// ---------------- main kernel (fully fused) -----------------------------------
__global__ __launch_bounds__(TPB, 12) void main_kernel(
    const float* __restrict__ pi,
    const float* __restrict__ mu,
    const float* __restrict__ L,
    const float* __restrict__ ef_logits,
    const float* __restrict__ tracks,
    const uint32_t* __restrict__ mask,
    float* __restrict__ out)
{
    const int bid  = blockIdx.x;
    const int b    = bid >> 1;
    const int half = bid & 1;
    const int tid  = threadIdx.x;

    __shared__ float4  scA[KK];        // {c0,c1,c2,c3} per k          4 KB
    __shared__ float4  scB[JP];        // {c4_k0,c5_k0,c4_k1,c5_k1}    2 KB
    __shared__ __half2 sceh[JP * CC];  // {ce(2j,g), ce(2j+1,g)} f16   3 KB
    __shared__ double  red[4 * 4];
    __shared__ bool    isLast;

    // Lambda contribution: only half 0 accumulates pi (each thread covers 2 k's)
    double lam = 0.0;
    if (half == 0) {
        lam = (double)pi[(size_t)b * KK + tid] + (double)pi[(size_t)b * KK + tid + TPB];
    }

    const int n0 = half * HALF_N;
    // prefix-mask property: first inactive => whole 256-track range inactive
    const bool blockActive = (mask[(size_t)b * NN + n0] != 0u);

    double spatial = 0.0, efs = 0.0, cnt = 0.0;

    if (blockActive) {
        // ---- staging (float): thread tid builds coefficients for k=tid, tid+128 ----
        #pragma unroll
        for (int kk = 0; kk < 2; kk++) {
            const int k = tid + kk * TPB;
            const int i = b * KK + k;
            float pv = pi[i];
            float a  = L[i * 4 + 0];
            float bb = L[i * 4 + 2];
            float c  = L[i * 4 + 3];
            float m0 = mu[i * 2 + 0];
            float m1 = mu[i * 2 + 1];

            float base2 = lg2f(pv) - LOG2PI_LOG2E_F - lg2f(a * c);  // < 0

            float A2  = RQ2_F / (a * a);
            float Cr2 = RQ2_F / (c * c);
            float BA  = bb / a;
            float P = fmaf(Cr2 * BA, BA, A2);
            float Q = Cr2;
            float R = -2.0f * Cr2 * BA;

            float4 v4;
            v4.x = base2 - P * m0 * m0 - Q * m1 * m1 - R * m0 * m1;
            v4.y = fmaf(2.0f * P, m0, R * m1);
            v4.z = fmaf(2.0f * Q, m1, R * m0);
            v4.w = -P;
            scA[k] = v4;

            const int j = k >> 1, lane = k & 1;
            float* fB = (float*)scB;
            fB[j * 4 + lane * 2 + 0] = -Q;
            fB[j * 4 + lane * 2 + 1] = -R;

            // CE table: lse(ef_logits) - ef_logits[c], paired f16 layout
            float e[CC];
            float mx = -INFINITY;
            #pragma unroll
            for (int c2 = 0; c2 < CC; c2++) {
                e[c2] = ef_logits[(size_t)i * CC + c2];
                mx = fmaxf(mx, e[c2]);
            }
            float ssum = 0.f;
            #pragma unroll
            for (int c2 = 0; c2 < CC; c2++) ssum += ex2f((e[c2] - mx) * LOG2E_F);
            float lse = mx + lg2f(ssum) * LN2_F;
            __half* hce = reinterpret_cast<__half*>(sceh);
            #pragma unroll
            for (int c2 = 0; c2 < CC; c2++)
                hce[(j * CC + c2) * 2 + lane] = __float2half_rn(lse - e[c2]);
        }
        __syncthreads();

        // ---- per-track pass: thread owns tracks n0+tid (A) and n0+tid+128 (B) ----
        const int nA = n0 + tid;
        const int nB = nA + TPB;
        const bool actA = (mask[(size_t)b * NN + nA] != 0u);
        const bool actB = (mask[(size_t)b * NN + nB] != 0u);
        const bool anyA = (__ballot_sync(0xffffffffu, actA) != 0u);
        const bool anyB = (__ballot_sync(0xffffffffu, actB) != 0u);

        if (anyA) {
            const float* trA = tracks + ((size_t)b * NN + nA) * 6;
            const float* trB = tracks + ((size_t)b * NN + nB) * 6;
            float x0A = trA[0], x1A = trA[1];
            int   gA  = (int)trA[5];
            const __half2* cepA = sceh + gA;

            float sA = 0.f, tA = 0.f;
            const __half2 hzero = __floats2half2_rn(0.f, 0.f);

            if (anyB) {
                float x0B = trB[0], x1B = trB[1];
                int   gB  = (int)trB[5];
                const __half2* cepB = sceh + gB;
                float sB = 0.f, tB = 0.f;

                for (int J = 0; J < JP; J += 16) {
                    __half2 sAh = hzero, tAh = hzero, sBh = hzero, tBh = hzero;
                    #pragma unroll 4
                    for (int j = J; j < J + 16; j++) {
                        const float4 a0  = scA[2 * j];
                        const float4 a1  = scA[2 * j + 1];
                        const float4 bbq = scB[j];
                        const __half2 ceA = cepA[j * CC];
                        const __half2 ceB = cepB[j * CC];

                        // Horner: q = c0 + (c1 + c3*x0)*x0 + (c2 + c5*x0 + c4*x1)*x1
                        float u1A = fmaf(a0.w, x0A, a0.y);
                        float u2A = fmaf(bbq.y, x0A, a0.z);
                        u2A = fmaf(bbq.x, x1A, u2A);
                        float qA0 = fmaf(u1A, x0A, a0.x);
                        qA0 = fmaf(u2A, x1A, qA0);

                        float u1B = fmaf(a0.w, x0B, a0.y);
                        float u2B = fmaf(bbq.y, x0B, a0.z);
                        u2B = fmaf(bbq.x, x1B, u2B);
                        float qB0 = fmaf(u1B, x0B, a0.x);
                        qB0 = fmaf(u2B, x1B, qB0);

                        float v1A = fmaf(a1.w, x0A, a1.y);
                        float v2A = fmaf(bbq.w, x0A, a1.z);
                        v2A = fmaf(bbq.z, x1A, v2A);
                        float qA1 = fmaf(v1A, x0A, a1.x);
                        qA1 = fmaf(v2A, x1A, qA1);

                        float v1B = fmaf(a1.w, x0B, a1.y);
                        float v2B = fmaf(bbq.w, x0B, a1.z);
                        v2B = fmaf(bbq.z, x1B, v2B);
                        float qB1 = fmaf(v1B, x0B, a1.x);
                        qB1 = fmaf(v2B, x1B, qB1);

                        __half2 pA = h2ex2(__floats2half2_rn(qA0, qA1));
                        __half2 pB = h2ex2(__floats2half2_rn(qB0, qB1));

                        sAh = __hadd2(sAh, pA);
                        sBh = __hadd2(sBh, pB);
                        tAh = __hfma2(pA, ceA, tAh);
                        tBh = __hfma2(pB, ceB, tBh);
                    }
                    float2 f;
                    f = __half22float2(sAh); sA += f.x + f.y;
                    f = __half22float2(tAh); tA += f.x + f.y;
                    f = __half22float2(sBh); sB += f.x + f.y;
                    f = __half22float2(tBh); tB += f.x + f.y;
                }
                if (actB) {
                    spatial -= (double)(lg2f(sB) * LN2_F);
                    efs     += (double)(tB / sB);
                    cnt     += 1.0;
                }
            } else {
                for (int J = 0; J < JP; J += 16) {
                    __half2 sAh = hzero, tAh = hzero;
                    #pragma unroll 4
                    for (int j = J; j < J + 16; j++) {
                        const float4 a0  = scA[2 * j];
                        const float4 a1  = scA[2 * j + 1];
                        const float4 bbq = scB[j];
                        const __half2 ceA = cepA[j * CC];

                        float u1A = fmaf(a0.w, x0A, a0.y);
                        float u2A = fmaf(bbq.y, x0A, a0.z);
                        u2A = fmaf(bbq.x, x1A, u2A);
                        float qA0 = fmaf(u1A, x0A, a0.x);
                        qA0 = fmaf(u2A, x1A, qA0);

                        float v1A = fmaf(a1.w, x0A, a1.y);
                        float v2A = fmaf(bbq.w, x0A, a1.z);
                        v2A = fmaf(bbq.z, x1A, v2A);
                        float qA1 = fmaf(v1A, x0A, a1.x);
                        qA1 = fmaf(v2A, x1A, qA1);

                        __half2 pA = h2ex2(__floats2half2_rn(qA0, qA1));
                        sAh = __hadd2(sAh, pA);
                        tAh = __hfma2(pA, ceA, tAh);
                    }
                    float2 f;
                    f = __half22float2(sAh); sA += f.x + f.y;
                    f = __half22float2(tAh); tA += f.x + f.y;
                }
            }
            if (actA) {
                spatial -= (double)(lg2f(sA) * LN2_F);
                efs     += (double)(tA / sA);
                cnt     += 1.0;
            }
        }
    }

    // ---- block reduce 4 doubles (uniform control, 4 warps) ----
    spatial = warpRedD(spatial);
    efs     = warpRedD(efs);
    cnt     = warpRedD(cnt);
    lam     = warpRedD(lam);
    const int wid = tid >> 5, lid = tid & 31;
    if (lid == 0) {
        red[wid]      = spatial;
        red[4 + wid]  = efs;
        red[8 + wid]  = cnt;
        red[12 + wid] = lam;
    }
    __syncthreads();
    if (tid == 0) {
        double s0 = 0, s1 = 0, s2 = 0, s3 = 0;
        #pragma unroll
        for (int w = 0; w < 4; w++) {
            s0 += red[w]; s1 += red[4 + w]; s2 += red[8 + w]; s3 += red[12 + w];
        }
        g_part[bid] = make_double4(s0, s1, s2, s3);
    }

    // ---- last-block-done finalize (deterministic fixed-order sum) ----
    __threadfence();
    if (tid == 0) {
        unsigned int v = atomicAdd(&g_done, 1u);
        isLast = (v == 2u * BB - 1u);
    }
    __syncthreads();
    if (isLast) {
        double lamSum = 0, cntSum = 0, l1Sum = 0, spSum = 0, efSum = 0;
        for (int b2 = tid; b2 < BB; b2 += TPB) {
            double4 e0 = g_part[2 * b2];
            double4 e1 = g_part[2 * b2 + 1];
            double sp = e0.x + e1.x;
            double ef = e0.y + e1.y;
            double gc = e0.z + e1.z;
            double lm = e0.w + e1.w;
            lamSum += lm;
            cntSum += gc;
            l1Sum  += fabs(lm - gc) * sqrt(gc + 1.0);
            spSum  += sp;
            efSum  += ef;
        }
        lamSum = warpRedD(lamSum);
        cntSum = warpRedD(cntSum);
        l1Sum  = warpRedD(l1Sum);
        spSum  = warpRedD(spSum);
        efSum  = warpRedD(efSum);
        __syncthreads();
        __shared__ double red5[4 * 5];
        if (lid == 0) {
            red5[wid]      = lamSum;
            red5[4 + wid]  = cntSum;
            red5[8 + wid]  = l1Sum;
            red5[12 + wid] = spSum;
            red5[16 + wid] = efSum;
        }
        __syncthreads();
        if (tid == 0) {
            double a0 = 0, a1 = 0, a2 = 0, a3 = 0, a4 = 0;
            #pragma unroll
            for (int w = 0; w < 4; w++) {
                a0 += red5[w]; a1 += red5[4 + w]; a2 += red5[8 + w];
                a3 += red5[12 + w]; a4 += red5[16 + w];
            }
            double count_loss = a0 / (double)BB;
            double n_total    = a1 > 1.0 ? a1 : 1.0;
            double count_l1   = a2 / (double)BB;
            double spatialL   = a3 / n_total;
            double efL        = a4 / n_total;
            double total = count_loss + spatialL + efL + count_l1;
            out[0] = (float)total;
            out[1] = (float)spatialL;
            out[2] = (float)count_loss;
            out[3] = (float)count_l1;
            out[4] = (float)efL;
            g_done = 0;  // reset for next graph replay
        }
    }
}

// ---------------- launch -------------------------------------------------------
extern "C" void kernel_launch(void* const* d_in, const int* in_sizes, int n_in,
                              void* d_out, int out_size) {
    const float* pi        = (const float*)d_in[0];
    const float* mu        = (const float*)d_in[1];
    const float* L         = (const float*)d_in[2];
    const float* ef_logits = (const float*)d_in[3];
    const float* tracks    = (const float*)d_in[4];
    const uint32_t* mask   = (const uint32_t*)d_in[5];

    main_kernel<<<2 * BB, TPB>>>(pi, mu, L, ef_logits, tracks, mask, (float*)d_out);
}